// round 7
// baseline (speedup 1.0000x reference)
#include <cuda_runtime.h>
#include <cstdint>
#include <math.h>

// Problem constants: N=9 board, C=81 cells.
#define CC 81
#define ND 17            // dy,dx in [-8,8]
#define NDIR (ND*ND)     // 289 distinct direction vectors
#define TPB 972          // 81 groups x 12 lanes

// ===========================================================================
// Compile-time geometry (identical to the round-6 verified tables).
// Replicates EXACTLY the fp32 decision pipeline of the verified kernels:
//   angle: da = atan2<double>(-dy,dx); raw = f32(da)*f32(180/pi);
//          ang = raw>0 ? raw : raw+360.0f                    (fp32 RN)
//   stable order: integer key dsq*81 + cell  (== stable argsort of fp32 dist)
//   base: dist=f32(sqrt(dsq)); b=(maxd-dist)/maxd; if (b<0.5f) b*=0.5f (fp32)
//   mask bit (i<j sorted): ad=|ang_i-ang_j| (wrap >180 -> 360-ad); ad < 45.0f
// ===========================================================================
constexpr double CPI = 3.14159265358979323846264338327950288;

constexpr double c_sqrt(double x) {
    if (x <= 0.0) return 0.0;
    double g = (x < 1.0) ? 1.0 : x;
    for (int i = 0; i < 30; i++) g = 0.5 * (g + x / g);
    return g;
}
constexpr double c_atan01(double z) {
    double r = z;
    for (int i = 0; i < 3; i++) r = r / (1.0 + c_sqrt(1.0 + r * r));
    double r2 = r * r, s = 0.0, term = r;
    for (int k = 0; k < 13; k++) {
        s += ((k & 1) ? -term : term) / (double)(2 * k + 1);
        term *= r2;
    }
    return 8.0 * s;
}
constexpr double c_atan2(double y, double x) {
    if (x == 0.0) return (y > 0.0) ? CPI * 0.5 : (y < 0.0 ? -CPI * 0.5 : 0.0);
    double ay = (y < 0.0) ? -y : y, ax = (x < 0.0) ? -x : x;
    double az = ay / ax;
    double a  = (az <= 1.0) ? c_atan01(az) : (CPI * 0.5 - c_atan01(1.0 / az));
    if (x < 0.0) a = CPI - a;
    return (y < 0.0) ? -a : a;
}

struct Tables {
    unsigned long long mlo[CC][CC];  // [a][sorted j]: bits i<j  (i in 0..63)
    unsigned long long mhi[CC][CC];  // [a][sorted j]: bits i-64
    unsigned long long tlo[CC][CC];  // [a][cell c]: bit j iff mask[a][j] has bit rank(c)
    unsigned long long thi[CC][CC];
    float              base[CC][CC]; // [a][sorted j]
    unsigned char      rank[CC][CC]; // [a][cell] -> sorted pos
};

constexpr Tables make_tables() {
    Tables tb{};
    float angt[NDIR] = {};
    for (int dy = -8; dy <= 8; dy++)
        for (int dx = -8; dx <= 8; dx++) {
            double da = c_atan2((double)(-dy), (double)dx);
            float raw = (float)da * 57.295779513082323f;
            angt[(dy + 8) * ND + (dx + 8)] = (raw > 0.0f) ? raw : raw + 360.0f;
        }
    unsigned long long adj[NDIR][5] = {};
    for (int u = 0; u < NDIR; u++)
        for (int v = 0; v < NDIR; v++) {
            float ad = angt[u] - angt[v];
            if (ad < 0.0f) ad = -ad;
            if (ad > 180.0f) ad = 360.0f - ad;
            if (ad < 45.0f) adj[u][v >> 6] |= 1ull << (v & 63);
        }
    for (int a = 0; a < CC; a++) {
        int ay = a / 9, ax = a % 9;
        int dsq[CC] = {}, dir[CC] = {};
        for (int c = 0; c < CC; c++) {
            int dy = c / 9 - ay, dx = c % 9 - ax;
            dsq[c] = dy * dy + dx * dx;
            dir[c] = (dy + 8) * ND + (dx + 8);
        }
        int start[130] = {};
        for (int c = 0; c < CC; c++) start[dsq[c] + 1]++;
        for (int d = 0; d < 129; d++) start[d + 1] += start[d];
        int sidx[CC] = {}, sdir[CC] = {};
        for (int c = 0; c < CC; c++) {
            int r = start[dsq[c]]++;
            tb.rank[a][c] = (unsigned char)r;
            sidx[r] = c;
            sdir[r] = dir[c];
            float dist = (float)c_sqrt((double)dsq[c]);
            float b_ = (12.727922061357855f - dist) / 12.727922061357855f;
            if (b_ < 0.5f) b_ = b_ * 0.5f;
            tb.base[a][r] = b_;
        }
        for (int j = 0; j < CC; j++) {
            const unsigned long long* row = adj[sdir[j]];
            for (int i = 0; i < j; i++) {
                int v = sdir[i];
                if ((row[v >> 6] >> (v & 63)) & 1ull) {
                    if (i < 64) tb.mlo[a][j] |= 1ull << i;
                    else        tb.mhi[a][j] |= 1ull << (i - 64);
                    int c = sidx[i];
                    if (j < 64) tb.tlo[a][c] |= 1ull << j;
                    else        tb.thi[a][c] |= 1ull << (j - 64);
                }
            }
        }
    }
    return tb;
}

__device__ constexpr Tables d_tab = make_tables();

// ===========================================================================
// Single-block fused kernel (one graph node, no memset, no global atomics).
// 972 threads = 81 groups x 12 lanes.
//  A: stone bitmasks per empty center (shared atomicOr)
//  B: negT[a][j] + cval partials per (center, stone cell)
//  C: C0[a] via fixed-order 12-lane reduction
//  D: per (candidate b, center a): Tb (ascending-j ffs) + recomputed selfT
//  E: out[b] = sum of 12 partials (or 0 for non-empty b) — direct STG
// All reduction orders are fixed -> fully deterministic output.
// ===========================================================================
__global__ void __launch_bounds__(TPB) fused_kernel(const float* __restrict__ board,
                                                    float* __restrict__ out) {
    __shared__ float negT2d[CC][CC];            // [a][sorted pos]  (26.2 KB)
    __shared__ float partial[CC][12];           // reduction staging
    __shared__ float C0[CC];
    __shared__ unsigned long long stm[CC][4];   // per-center stone masks
    __shared__ signed char bv[CC];

    const int t = threadIdx.x;
    const int g = t / 12;     // group: center a (A-C) / candidate b (D)
    const int l = t % 12;

    if (t < CC) bv[t] = (signed char)(int)board[t];
    if (t < CC * 4) stm[t >> 2][t & 3] = 0ull;
    __syncthreads();

    // -- Phase A: stone masks for empty centers ----------------------------
    if (bv[g] == 0) {
        for (int c = l; c < CC; c += 12) {
            int v = (int)bv[c];
            if (v != 0) {
                int r = (int)d_tab.rank[g][c];
                atomicOr(&stm[g][(v < 0 ? 0 : 2) + (r >= 64)], 1ull << (r & 63));
            }
        }
    }
    __syncthreads();

    // -- Phase B: negT + cval partials -------------------------------------
    {
        float cv = 0.0f;
        if (bv[g] == 0) {
            const unsigned long long nLo = stm[g][0], nHi = stm[g][1];
            const unsigned long long pLo = stm[g][2], pHi = stm[g][3];
            for (int c = l; c < CC; c += 12) {
                int v = (int)bv[c];
                if (v != 0) {
                    int r = (int)d_tab.rank[g][c];
                    unsigned long long Mlo = d_tab.mlo[g][r], Mhi = d_tab.mhi[g][r];
                    float bs = d_tab.base[g][r];
                    if (v > 0) {
                        int kneg = __popcll(Mlo & nLo) + __popcll(Mhi & nHi);
                        cv += bs * exp2f(-(float)kneg);
                    } else {
                        int kpos = __popcll(Mlo & pLo) + __popcll(Mhi & pHi);
                        float nt = bs * exp2f(-(float)kpos);
                        negT2d[g][r] = nt;
                        cv -= nt;
                    }
                }
            }
        }
        partial[g][l] = cv;
    }
    __syncthreads();

    // -- Phase C: C0 per center (fixed order) ------------------------------
    if (t < CC) {
        float s = 0.0f;
        #pragma unroll
        for (int q = 0; q < 12; q++) s += partial[t][q];
        C0[t] = s;
    }
    __syncthreads();

    // -- Phase D: per (b=g, a=l+12k) contributions -------------------------
    {
        float acc = 0.0f;
        if (bv[g] == 0) {
            for (int a = l; a < CC; a += 12) {
                if (a == g || bv[a] != 0) continue;
                const unsigned long long nLo = stm[a][0], nHi = stm[a][1];
                unsigned long long m  = d_tab.tlo[a][g] & nLo;
                unsigned long long m2 = d_tab.thi[a][g] & nHi;
                float Tb = 0.0f;
                while (m)  { int j = __ffsll((long long)m)  - 1; Tb += negT2d[a][j];      m  &= m  - 1; }
                while (m2) { int j = __ffsll((long long)m2) - 1; Tb += negT2d[a][j + 64]; m2 &= m2 - 1; }
                int r = (int)d_tab.rank[a][g];
                int kneg = __popcll(d_tab.mlo[a][r] & nLo) + __popcll(d_tab.mhi[a][r] & nHi);
                float st = d_tab.base[a][r] * exp2f(-(float)kneg);   // selfT
                acc += C0[a] + 0.5f * Tb + st;
            }
        }
        partial[g][l] = acc;     // exclusive writer per (g,l); C-phase reads done
    }
    __syncthreads();

    // -- Phase E: final output (zeros included — no memset node needed) ----
    if (t < CC) {
        float s = 0.0f;
        if (bv[t] == 0) {
            #pragma unroll
            for (int q = 0; q < 12; q++) s += partial[t][q];
        }
        out[t] = s;
    }
}

// ---------------------------------------------------------------------------
// kernel_launch: graph-capturable, allocation-free, deterministic.
// Inputs (metadata order): all_coords int32[243], board float32[81].
// ---------------------------------------------------------------------------
extern "C" void kernel_launch(void* const* d_in, const int* in_sizes, int n_in,
                              void* d_out, int out_size) {
    const float* board = nullptr;
    for (int i = 0; i < n_in; i++) {
        if (in_sizes[i] == 81) { board = (const float*)d_in[i]; break; }
    }
    if (!board) board = (const float*)d_in[n_in - 1];

    fused_kernel<<<1, TPB>>>(board, (float*)d_out);
}

// round 9
// speedup vs baseline: 2.1701x; 2.1701x over previous
#include <cuda_runtime.h>
#include <cstdint>
#include <math.h>

// Problem constants: N=9 board, C=81 cells.
#define CC 81
#define ND 17            // dy,dx in [-8,8]
#define NDIR (ND*ND)     // 289 distinct direction vectors

// ===========================================================================
// Compile-time geometry in CELL space (no runtime rank lookups).
//   cmask[a][c]: bit d set iff  key[d] < key[c]  (stable-closer at center a)
//                AND fp32 angle separation of directions (a->d),(a->c) < 45.
//   baseC[a][c]: distance base weight of cell c at center a.
// The fp32 decision pipeline (angle table, 45-deg compare, base weights,
// stable integer sort key dsq*81+cell) is IDENTICAL to the round-6 verified
// tables (rel_err = 8.35e-4); only the indexing changed from sorted-position
// space to cell space, which is a pure re-labeling.
// ===========================================================================
constexpr double CPI = 3.14159265358979323846264338327950288;

constexpr double c_sqrt(double x) {
    if (x <= 0.0) return 0.0;
    double g = (x < 1.0) ? 1.0 : x;
    for (int i = 0; i < 30; i++) g = 0.5 * (g + x / g);
    return g;
}
constexpr double c_atan01(double z) {
    double r = z;
    for (int i = 0; i < 3; i++) r = r / (1.0 + c_sqrt(1.0 + r * r));
    double r2 = r * r, s = 0.0, term = r;
    for (int k = 0; k < 13; k++) {
        s += ((k & 1) ? -term : term) / (double)(2 * k + 1);
        term *= r2;
    }
    return 8.0 * s;
}
constexpr double c_atan2(double y, double x) {
    if (x == 0.0) return (y > 0.0) ? CPI * 0.5 : (y < 0.0 ? -CPI * 0.5 : 0.0);
    double ay = (y < 0.0) ? -y : y, ax = (x < 0.0) ? -x : x;
    double az = ay / ax;
    double a  = (az <= 1.0) ? c_atan01(az) : (CPI * 0.5 - c_atan01(1.0 / az));
    if (x < 0.0) a = CPI - a;
    return (y < 0.0) ? -a : a;
}

struct Tables {
    unsigned long long cmlo[CC][CC];  // [a][c]: bits d in 0..63
    unsigned long long cmhi[CC][CC];  // [a][c]: bits d-64
    float              baseC[CC][CC]; // [a][c]
};

constexpr Tables make_tables() {
    Tables tb{};
    float angt[NDIR] = {};
    for (int dy = -8; dy <= 8; dy++)
        for (int dx = -8; dx <= 8; dx++) {
            double da = c_atan2((double)(-dy), (double)dx);
            float raw = (float)da * 57.295779513082323f;
            angt[(dy + 8) * ND + (dx + 8)] = (raw > 0.0f) ? raw : raw + 360.0f;
        }
    // Direction-pair 45-degree adjacency, packed (automatic storage).
    unsigned long long adj[NDIR][5] = {};
    for (int u = 0; u < NDIR; u++)
        for (int v = 0; v < NDIR; v++) {
            float ad = angt[u] - angt[v];
            if (ad < 0.0f) ad = -ad;
            if (ad > 180.0f) ad = 360.0f - ad;
            if (ad < 45.0f) adj[u][v >> 6] |= 1ull << (v & 63);
        }
    for (int a = 0; a < CC; a++) {
        int ay = a / 9, ax = a % 9;
        int key[CC] = {}, dir[CC] = {};
        for (int c = 0; c < CC; c++) {
            int dy = c / 9 - ay, dx = c % 9 - ax;
            key[c] = (dy * dy + dx * dx) * CC + c;   // stable argsort key
            dir[c] = (dy + 8) * ND + (dx + 8);
        }
        for (int c = 0; c < CC; c++) {
            float dist = (float)c_sqrt((double)(key[c] / CC));
            float b_ = (12.727922061357855f - dist) / 12.727922061357855f;
            if (b_ < 0.5f) b_ = b_ * 0.5f;
            tb.baseC[a][c] = b_;
            const unsigned long long* row = adj[dir[c]];
            for (int d = 0; d < CC; d++) {
                if (key[d] < key[c] && ((row[dir[d] >> 6] >> (dir[d] & 63)) & 1ull)) {
                    if (d < 64) tb.cmlo[a][c] |= 1ull << d;
                    else        tb.cmhi[a][c] |= 1ull << (d - 64);
                }
            }
        }
    }
    return tb;
}

__device__ constexpr Tables d_tab = make_tables();

// Exact 2^-k for integer k (attainable k <= 54): no MUFU, 2 ALU ops.
__device__ __forceinline__ float exp2i_neg(int k) {
    return __int_as_float((127 - k) << 23);
}

// ===========================================================================
// One block per candidate b; fully independent; writes out[b] directly
// (zeros for non-empty b) -> single graph node, no memset, no global atomics.
//   out[b] = sum over empty a != b, stones c:
//     v>0: +baseC[a][c] * 2^-popc(cmask[a][c] & neg)
//     v<0: -baseC[a][c] * 2^-popc(cmask[a][c] & pos) * (bit_b(cmask)?0.5:1)
//   plus per empty a != b: +baseC[a][b] * 2^-popc(cmask[a][b] & neg)
// All reductions are fixed-order -> deterministic.
// ===========================================================================
__global__ void __launch_bounds__(96) fused_kernel(const float* __restrict__ board,
                                                   float* __restrict__ out) {
    __shared__ signed char   bvs[CC];
    __shared__ unsigned int  wbe[3], wbneg[3], wbpos[3];  // per-warp ballots
    __shared__ unsigned char emptyL[CC], stoneL[CC];
    __shared__ float         warpsum[3];

    const int b    = blockIdx.x;
    const int t    = threadIdx.x;
    const int lane = t & 31, w = t >> 5;

    if (t < CC) bvs[t] = (signed char)(int)board[t];
    __syncthreads();

    if (bvs[b] != 0) {                 // non-empty candidate -> exact 0
        if (t == 0) out[b] = 0.0f;
        return;
    }

    // Warp ballots over cell occupancy (threads >= 81 excluded by 'valid').
    const bool valid = (t < CC);
    const int  v     = valid ? (int)bvs[t] : 1;
    unsigned be = __ballot_sync(0xffffffffu, valid && v == 0);
    unsigned bn = __ballot_sync(0xffffffffu, valid && v <  0);
    unsigned bp = __ballot_sync(0xffffffffu, valid && v >  0);
    if (lane == 0) { wbe[w] = be; wbneg[w] = bn; wbpos[w] = bp; }
    __syncthreads();

    // Board stone masks in cell space (identical in every thread).
    const unsigned long long negLo = (unsigned long long)wbneg[0]
                                   | ((unsigned long long)wbneg[1] << 32);
    const unsigned long long negHi = (unsigned long long)wbneg[2];
    const unsigned long long posLo = (unsigned long long)wbpos[0]
                                   | ((unsigned long long)wbpos[1] << 32);
    const unsigned long long posHi = (unsigned long long)wbpos[2];

    // Deterministic compaction of empty / stone cell lists (ascending cell
    // order). Warps 0,1 hold 32 cells each; warp 2 holds cells 64..80 (17).
    int nE = __popc(wbe[0]) + __popc(wbe[1]) + __popc(wbe[2]);
    int nS = CC - nE;
    if (valid) {
        unsigned lower = (lane ? (0xffffffffu >> (32 - lane)) : 0u);
        int before = 0;
        for (int q = 0; q < w; q++)                  // q only reaches 0,1
            before += (v == 0) ? __popc(wbe[q]) : (32 - __popc(wbe[q]));
        if (v == 0) {
            emptyL[before + __popc(be & lower)] = (unsigned char)t;
        } else {
            unsigned validmask = (w == 2 ? 0x1ffffu : 0xffffffffu);
            stoneL[before + __popc((~be) & lower & validmask)] = (unsigned char)t;
        }
    }
    __syncthreads();

    const unsigned long long bbit_lo = (b < 64) ? (1ull << b) : 0ull;
    const unsigned long long bbit_hi = (b < 64) ? 0ull : (1ull << (b - 64));

    float acc = 0.0f;
    const int nPairs = nE * nS;
    for (int idx = t; idx < nPairs; idx += 96) {
        int ei = idx / nS;
        int si = idx - ei * nS;
        int a  = (int)emptyL[ei];
        if (a == b) continue;
        int c  = (int)stoneL[si];
        unsigned long long mlo = d_tab.cmlo[a][c];
        unsigned long long mhi = d_tab.cmhi[a][c];
        float bs = d_tab.baseC[a][c];
        if ((int)bvs[c] > 0) {
            int k = __popcll(mlo & negLo) + __popcll(mhi & negHi);
            acc += bs * exp2i_neg(k);
        } else {
            int k = __popcll(mlo & posLo) + __popcll(mhi & posHi);
            float scale = ((mlo & bbit_lo) | (mhi & bbit_hi)) ? 0.5f : 1.0f;
            acc -= bs * exp2i_neg(k) * scale;
        }
    }
    // Self terms: hypothetical +1 stone at b as seen from each empty center a.
    for (int ei = t; ei < nE; ei += 96) {
        int a = (int)emptyL[ei];
        if (a == b) continue;
        int k = __popcll(d_tab.cmlo[a][b] & negLo)
              + __popcll(d_tab.cmhi[a][b] & negHi);
        acc += d_tab.baseC[a][b] * exp2i_neg(k);
    }

    // Fixed-order block reduction (3 warps).
    for (int o = 16; o; o >>= 1) acc += __shfl_down_sync(0xffffffffu, acc, o);
    if (lane == 0) warpsum[w] = acc;
    __syncthreads();
    if (t == 0) out[b] = warpsum[0] + warpsum[1] + warpsum[2];
}

// ---------------------------------------------------------------------------
// kernel_launch: graph-capturable, allocation-free, deterministic.
// Inputs (metadata order): all_coords int32[243], board float32[81].
// ---------------------------------------------------------------------------
extern "C" void kernel_launch(void* const* d_in, const int* in_sizes, int n_in,
                              void* d_out, int out_size) {
    const float* board = nullptr;
    for (int i = 0; i < n_in; i++) {
        if (in_sizes[i] == 81) { board = (const float*)d_in[i]; break; }
    }
    if (!board) board = (const float*)d_in[n_in - 1];

    fused_kernel<<<81, 96>>>(board, (float*)d_out);
}